// round 1
// baseline (speedup 1.0000x reference)
#include <cuda_runtime.h>
#include <cuda_bf16.h>
#include <math.h>

#define NN 50000
#define EE 800000
#define GG 512
#define HH 256
#define TT 32
#define LL 4

// ---------------- scratch (device globals; no allocations allowed) ----------
__device__ float g_bufA[NN * HH];
__device__ float g_bufB[NN * HH];
__device__ float g_bufC[NN * HH];
__device__ int   g_cnt[NN];
__device__ int   g_cnt2[NN];
__device__ int   g_rowptr[NN + 1];
__device__ int   g_csr[EE];
__device__ int   g_gcnt[GG];
__device__ int   g_goff[GG + 1];
__device__ float g_dinv[NN];
__device__ float g_P[100 * HH];
__device__ float g_Q[3 * HH];
__device__ float g_sums[2 * HH];
__device__ float g_pooled[GG * HH];

// ---------------- setup kernels ---------------------------------------------
__global__ void k_zero_init(int* cnt, int* cnt2, int* gcnt) {
    int i = blockIdx.x * blockDim.x + threadIdx.x;
    if (i < NN) { cnt[i] = 0; cnt2[i] = 0; }
    if (i < GG) gcnt[i] = 0;
}

__global__ void k_count_deg(const int* __restrict__ dst, int* cnt) {
    int e = blockIdx.x * blockDim.x + threadIdx.x;
    if (e < EE) atomicAdd(&cnt[dst[e]], 1);
}

__global__ void k_count_graph(const int* __restrict__ batch, int* gcnt) {
    int i = blockIdx.x * blockDim.x + threadIdx.x;
    if (i < NN) atomicAdd(&gcnt[batch[i]], 1);
}

__global__ void k_dinv(const int* __restrict__ cnt, float* dinv) {
    int i = blockIdx.x * blockDim.x + threadIdx.x;
    if (i < NN) dinv[i] = rsqrtf((float)cnt[i] + 1.0f);
}

// single-block inclusive scan -> rowptr (exclusive prefix of counts)
__global__ void k_scan_rowptr(const int* __restrict__ cnt, int* rowptr) {
    __shared__ int sh[1024];
    __shared__ int carry;
    const int tid = threadIdx.x;
    if (tid == 0) { carry = 0; rowptr[0] = 0; }
    __syncthreads();
    for (int base = 0; base < NN; base += 1024) {
        int i = base + tid;
        int v = (i < NN) ? cnt[i] : 0;
        sh[tid] = v;
        __syncthreads();
        for (int off = 1; off < 1024; off <<= 1) {
            int t = (tid >= off) ? sh[tid - off] : 0;
            __syncthreads();
            sh[tid] += t;
            __syncthreads();
        }
        int c = carry;
        if (i < NN) rowptr[i + 1] = sh[tid] + c;
        __syncthreads();
        if (tid == 0) carry = c + sh[1023];
        __syncthreads();
    }
}

__global__ void k_scan_goff(const int* __restrict__ gcnt, int* goff) {
    __shared__ int sh[GG];
    const int tid = threadIdx.x;
    sh[tid] = gcnt[tid];
    __syncthreads();
    for (int off = 1; off < GG; off <<= 1) {
        int t = (tid >= off) ? sh[tid - off] : 0;
        __syncthreads();
        sh[tid] += t;
        __syncthreads();
    }
    if (tid == 0) goff[0] = 0;
    goff[tid + 1] = sh[tid];
}

__global__ void k_fill_csr(const int* __restrict__ src, const int* __restrict__ dst,
                           const int* __restrict__ rowptr, int* cnt2, int* csr) {
    int e = blockIdx.x * blockDim.x + threadIdx.x;
    if (e < EE) {
        int d = dst[e];
        int pos = rowptr[d] + atomicAdd(&cnt2[d], 1);
        csr[pos] = src[e];
    }
}

// ---------------- projection tables + embed ---------------------------------
// P[r] = atom_emb[r] @ Wp[0:256];  Q[t] = tag_emb[t] @ Wp[256:288] + bp
__global__ void k_proj_tables(const float* __restrict__ atom_emb,
                              const float* __restrict__ tag_emb,
                              const float* __restrict__ Wp,
                              const float* __restrict__ bp,
                              float* P, float* Q) {
    int r = blockIdx.x;
    int c = threadIdx.x;
    if (r < 100) {
        float acc = 0.f;
        #pragma unroll 8
        for (int k = 0; k < HH; k++) acc += atom_emb[r * HH + k] * Wp[k * HH + c];
        P[r * HH + c] = acc;
    } else {
        int t = r - 100;
        if (t < 3) {
            float acc = bp[c];
            #pragma unroll
            for (int k = 0; k < TT; k++) acc += tag_emb[t * TT + k] * Wp[(HH + k) * HH + c];
            Q[t * HH + c] = acc;
        }
    }
}

__global__ void k_embed(const int* __restrict__ x, const int* __restrict__ tags,
                        const float* __restrict__ P, const float* __restrict__ Q,
                        float* __restrict__ h) {
    int node = blockIdx.x;
    int c = threadIdx.x;
    h[node * HH + c] = P[x[node] * HH + c] + Q[tags[node] * HH + c];
}

// ---------------- SGEMM: C[M,256] = A[M,256] @ B[256,256] -------------------
__global__ __launch_bounds__(256) void k_sgemm(const float* __restrict__ A,
                                               const float* __restrict__ B,
                                               float* __restrict__ C, int M) {
    __shared__ float As[8][128];
    __shared__ float Bs[8][128];
    const int tid = threadIdx.x;
    const int bm = blockIdx.y * 128;
    const int bn = blockIdx.x * 128;
    const int arow = tid >> 1;
    const int acol = (tid & 1) * 4;
    const int brow = tid >> 5;
    const int bcol = (tid & 31) * 4;
    const int ty = tid >> 4, tx = tid & 15;
    const int trow = ty * 8, tcol = tx * 8;

    float acc[8][8];
    #pragma unroll
    for (int i = 0; i < 8; i++)
        #pragma unroll
        for (int j = 0; j < 8; j++) acc[i][j] = 0.f;

    const bool aval = (bm + arow) < M;
    const float* Aptr = A + (size_t)(bm + arow) * HH;

    for (int k0 = 0; k0 < HH; k0 += 8) {
        float4 av = aval ? *(const float4*)(Aptr + k0 + acol) : make_float4(0.f, 0.f, 0.f, 0.f);
        As[acol + 0][arow] = av.x;
        As[acol + 1][arow] = av.y;
        As[acol + 2][arow] = av.z;
        As[acol + 3][arow] = av.w;
        float4 bv = *(const float4*)(B + (size_t)(k0 + brow) * HH + bn + bcol);
        *(float4*)&Bs[brow][bcol] = bv;
        __syncthreads();
        #pragma unroll
        for (int kk = 0; kk < 8; kk++) {
            float a[8], b[8];
            *(float4*)&a[0] = *(float4*)&As[kk][trow];
            *(float4*)&a[4] = *(float4*)&As[kk][trow + 4];
            *(float4*)&b[0] = *(float4*)&Bs[kk][tcol];
            *(float4*)&b[4] = *(float4*)&Bs[kk][tcol + 4];
            #pragma unroll
            for (int i = 0; i < 8; i++)
                #pragma unroll
                for (int j = 0; j < 8; j++) acc[i][j] += a[i] * b[j];
        }
        __syncthreads();
    }
    #pragma unroll
    for (int i = 0; i < 8; i++) {
        int row = bm + trow + i;
        if (row < M) {
            *(float4*)(C + (size_t)row * HH + bn + tcol)     = *(float4*)&acc[i][0];
            *(float4*)(C + (size_t)row * HH + bn + tcol + 4) = *(float4*)&acc[i][4];
        }
    }
}

// ---------------- GCN aggregation (CSR, block per node) ---------------------
__global__ void k_aggregate(const float* __restrict__ hw, const float* __restrict__ dinv,
                            const int* __restrict__ rowptr, const int* __restrict__ csr,
                            const float* __restrict__ bias, float* __restrict__ agg) {
    const int v = blockIdx.x;
    const int c = threadIdx.x;
    const float dv = dinv[v];
    float acc = hw[(size_t)v * HH + c] * dv * dv;
    const int s0 = rowptr[v], s1 = rowptr[v + 1];
    __shared__ int   ssrc[256];
    __shared__ float sw[256];
    for (int base = s0; base < s1; base += 256) {
        int n = min(256, s1 - base);
        if (c < n) {
            int s = csr[base + c];
            ssrc[c] = s;
            sw[c] = dinv[s] * dv;
        }
        __syncthreads();
        #pragma unroll 4
        for (int j = 0; j < n; j++)
            acc += hw[(size_t)ssrc[j] * HH + c] * sw[j];
        __syncthreads();
    }
    agg[(size_t)v * HH + c] = acc + bias[c];
}

// ---------------- batch norm ------------------------------------------------
__global__ void k_zero_sums(float* sums) { sums[threadIdx.x] = 0.f; }

__global__ void k_bn_stats(const float* __restrict__ agg, float* sums) {
    const int c = threadIdx.x;
    float s = 0.f, s2 = 0.f;
    for (int r = blockIdx.x; r < NN; r += gridDim.x) {
        float v = agg[(size_t)r * HH + c];
        s += v;
        s2 += v * v;
    }
    atomicAdd(&sums[c], s);
    atomicAdd(&sums[HH + c], s2);
}

__global__ void k_bn_apply(const float* __restrict__ agg, const float* __restrict__ hres,
                           const float* __restrict__ sums,
                           const float* __restrict__ g, const float* __restrict__ b,
                           float* __restrict__ hout) {
    const int idx = blockIdx.x * blockDim.x + threadIdx.x;
    const int c = idx & (HH - 1);
    const float inv_n = 1.0f / (float)NN;
    float mu = sums[c] * inv_n;
    float var = sums[HH + c] * inv_n - mu * mu;
    float val = (agg[idx] - mu) * rsqrtf(var + 1e-5f) * g[c] + b[c];
    val = fmaxf(val, 0.f) + hres[idx];
    hout[idx] = val;
}

// ---------------- pooling + MLP ---------------------------------------------
__global__ void k_pool(const float* __restrict__ h, const int* __restrict__ goff,
                       float* __restrict__ pooled) {
    const int gidx = blockIdx.x;
    const int c = threadIdx.x;
    const int s = goff[gidx], e = goff[gidx + 1];
    float acc = 0.f;
    for (int r = s; r < e; r++) acc += h[(size_t)r * HH + c];
    float cnt = (float)(e - s);
    pooled[gidx * HH + c] = acc / fmaxf(cnt, 1.0f);
}

__global__ void k_mlp(const float* __restrict__ pooled,
                      const float* __restrict__ W1, const float* __restrict__ b1,
                      const float* __restrict__ W2, const float* __restrict__ b2,
                      float* __restrict__ out) {
    const int gidx = blockIdx.x;
    const int t = threadIdx.x;  // 128
    __shared__ float sp[HH];
    __shared__ float red[128];
    sp[t] = pooled[gidx * HH + t];
    sp[t + 128] = pooled[gidx * HH + t + 128];
    __syncthreads();
    float acc = b1[t];
    #pragma unroll 8
    for (int k = 0; k < HH; k++) acc += sp[k] * W1[k * 128 + t];
    acc = fmaxf(acc, 0.f);
    red[t] = acc * W2[t];
    __syncthreads();
    for (int off = 64; off > 0; off >>= 1) {
        if (t < off) red[t] += red[t + off];
        __syncthreads();
    }
    if (t == 0) out[gidx] = red[0] + b2[0];
}

// ---------------- launch ----------------------------------------------------
extern "C" void kernel_launch(void* const* d_in, const int* in_sizes, int n_in,
                              void* d_out, int out_size) {
    const int*   x        = (const int*)d_in[0];
    const int*   tags     = (const int*)d_in[1];
    const int*   eidx     = (const int*)d_in[2];
    const int*   batch    = (const int*)d_in[3];
    const float* atom_emb = (const float*)d_in[4];
    const float* tag_emb  = (const float*)d_in[5];
    const float* Wp       = (const float*)d_in[6];
    const float* bp       = (const float*)d_in[7];
    const float* gcn_W    = (const float*)d_in[8];
    const float* gcn_b    = (const float*)d_in[9];
    const float* bn_g     = (const float*)d_in[10];
    const float* bn_b     = (const float*)d_in[11];
    const float* W1       = (const float*)d_in[12];
    const float* b1       = (const float*)d_in[13];
    const float* W2       = (const float*)d_in[14];
    const float* b2       = (const float*)d_in[15];
    float* out = (float*)d_out;

    const int* src = eidx;
    const int* dst = eidx + EE;

    float *bufA, *bufB, *bufC, *dinv, *P, *Q, *sums, *pooled;
    int *cnt, *cnt2, *rowptr, *csr, *gcnt, *goff;
    cudaGetSymbolAddress((void**)&bufA, g_bufA);
    cudaGetSymbolAddress((void**)&bufB, g_bufB);
    cudaGetSymbolAddress((void**)&bufC, g_bufC);
    cudaGetSymbolAddress((void**)&cnt, g_cnt);
    cudaGetSymbolAddress((void**)&cnt2, g_cnt2);
    cudaGetSymbolAddress((void**)&rowptr, g_rowptr);
    cudaGetSymbolAddress((void**)&csr, g_csr);
    cudaGetSymbolAddress((void**)&gcnt, g_gcnt);
    cudaGetSymbolAddress((void**)&goff, g_goff);
    cudaGetSymbolAddress((void**)&dinv, g_dinv);
    cudaGetSymbolAddress((void**)&P, g_P);
    cudaGetSymbolAddress((void**)&Q, g_Q);
    cudaGetSymbolAddress((void**)&sums, g_sums);
    cudaGetSymbolAddress((void**)&pooled, g_pooled);

    const int TB = 256;
    // setup: degrees, CSR, graph offsets
    k_zero_init<<<(NN + TB - 1) / TB, TB>>>(cnt, cnt2, gcnt);
    k_count_deg<<<(EE + TB - 1) / TB, TB>>>(dst, cnt);
    k_count_graph<<<(NN + TB - 1) / TB, TB>>>(batch, gcnt);
    k_dinv<<<(NN + TB - 1) / TB, TB>>>(cnt, dinv);
    k_scan_rowptr<<<1, 1024>>>(cnt, rowptr);
    k_scan_goff<<<1, GG>>>(gcnt, goff);
    k_fill_csr<<<(EE + TB - 1) / TB, TB>>>(src, dst, rowptr, cnt2, csr);

    // projection (as table lookup) -> h0 in bufA
    k_proj_tables<<<103, HH>>>(atom_emb, tag_emb, Wp, bp, P, Q);
    k_embed<<<NN, HH>>>(x, tags, P, Q, bufA);

    float* h  = bufA;
    float* hw = bufB;
    float* agg = bufC;
    dim3 ggrid(2, (NN + 127) / 128);
    for (int l = 0; l < LL; l++) {
        k_sgemm<<<ggrid, 256>>>(h, gcn_W + (size_t)l * HH * HH, hw, NN);
        k_zero_sums<<<1, 2 * HH>>>(sums);
        k_aggregate<<<NN, HH>>>(hw, dinv, rowptr, csr, gcn_b + l * HH, agg);
        k_bn_stats<<<512, HH>>>(agg, sums);
        k_bn_apply<<<(NN * HH) / TB, TB>>>(agg, h, sums, bn_g + l * HH, bn_b + l * HH, hw);
        // new h is in hw's buffer; old h buffer becomes scratch for next hw
        float* tmp = h; h = hw; hw = tmp;
    }

    k_pool<<<GG, HH>>>(h, goff, pooled);
    k_mlp<<<GG, 128>>>(pooled, W1, b1, W2, b2, out);
    (void)in_sizes; (void)n_in; (void)out_size;
}

// round 3
// speedup vs baseline: 1.2007x; 1.2007x over previous
#include <cuda_runtime.h>
#include <cuda_bf16.h>
#include <math.h>
#include <stdint.h>

#define NN 50000
#define EE 800000
#define GG 512
#define HH 256
#define TT 32
#define LL 4

// ---------------- scratch (device globals; no allocations allowed) ----------
__device__ float g_bufA[NN * HH];
__device__ float g_bufB[NN * HH];
__device__ float g_bufC[NN * HH];
__device__ int   g_cnt[NN];
__device__ int   g_cnt2[NN];
__device__ int   g_rowptr[NN + 1];
__device__ int   g_csr[EE];
__device__ int   g_gcnt[GG];
__device__ int   g_goff[GG + 1];
__device__ float g_dinv[NN];
__device__ float g_P[100 * HH];
__device__ float g_Q[3 * HH];
__device__ float g_sums[2 * HH];
__device__ float g_pooled[GG * HH];
// Pre-swizzled bf16 hi/lo images of W^T: [L][kc=4][split=2][n=256][64k*2B] = 1MB
__device__ unsigned char g_Wimg[LL * 4 * 2 * 32768];

// ---------------- helpers ----------------------------------------------------
__device__ __forceinline__ uint32_t smem_u32(const void* p) {
    uint32_t a;
    asm("{ .reg .u64 t; cvta.to.shared.u64 t, %1; cvt.u32.u64 %0, t; }" : "=r"(a) : "l"(p));
    return a;
}
__device__ __forceinline__ uint32_t swz128(uint32_t o) { return o ^ ((o >> 3) & 0x70); }

__device__ __forceinline__ void ldsm4(uint32_t* r, uint32_t addr) {
    asm volatile("ldmatrix.sync.aligned.m8n8.x4.shared.b16 {%0,%1,%2,%3}, [%4];"
        : "=r"(r[0]), "=r"(r[1]), "=r"(r[2]), "=r"(r[3]) : "r"(addr));
}
__device__ __forceinline__ void mma16816(float* d, const uint32_t* a, const uint32_t* b) {
    asm volatile("mma.sync.aligned.m16n8k16.row.col.f32.bf16.bf16.f32 "
        "{%0,%1,%2,%3}, {%4,%5,%6,%7}, {%8,%9}, {%0,%1,%2,%3};"
        : "+f"(d[0]), "+f"(d[1]), "+f"(d[2]), "+f"(d[3])
        : "r"(a[0]), "r"(a[1]), "r"(a[2]), "r"(a[3]), "r"(b[0]), "r"(b[1]));
}
__device__ __forceinline__ uint32_t pack_bf16x2(float lo, float hi) {
    __nv_bfloat16 a = __float2bfloat16(lo);
    __nv_bfloat16 b = __float2bfloat16(hi);
    return ((uint32_t)__bfloat16_as_ushort(b) << 16) | __bfloat16_as_ushort(a);
}

// ---------------- setup kernels ---------------------------------------------
__global__ void k_zero_init(int* cnt, int* cnt2, int* gcnt) {
    int i = blockIdx.x * blockDim.x + threadIdx.x;
    if (i < NN) { cnt[i] = 0; cnt2[i] = 0; }
    if (i < GG) gcnt[i] = 0;
}

__global__ void k_count(const int* __restrict__ dst, const int* __restrict__ batch,
                        int* cnt, int* gcnt) {
    int e = blockIdx.x * blockDim.x + threadIdx.x;
    if (e < EE) atomicAdd(&cnt[dst[e]], 1);
    if (e < NN) atomicAdd(&gcnt[batch[e]], 1);
}

// single block: rowptr scan + dinv + goff scan
__global__ void k_scan(const int* __restrict__ cnt, int* rowptr, float* dinv,
                       const int* __restrict__ gcnt, int* goff) {
    __shared__ int sh[1024];
    __shared__ int carry;
    const int tid = threadIdx.x;
    if (tid == 0) { carry = 0; rowptr[0] = 0; }
    __syncthreads();
    for (int base = 0; base < NN; base += 1024) {
        int i = base + tid;
        int v = (i < NN) ? cnt[i] : 0;
        if (i < NN) dinv[i] = rsqrtf((float)v + 1.0f);
        sh[tid] = v;
        __syncthreads();
        for (int off = 1; off < 1024; off <<= 1) {
            int t = (tid >= off) ? sh[tid - off] : 0;
            __syncthreads();
            sh[tid] += t;
            __syncthreads();
        }
        int c = carry;
        if (i < NN) rowptr[i + 1] = sh[tid] + c;
        __syncthreads();
        if (tid == 0) carry = c + sh[1023];
        __syncthreads();
    }
    // goff scan (512 entries padded to 1024)
    int vv = (tid < GG) ? gcnt[tid] : 0;
    sh[tid] = vv;
    __syncthreads();
    for (int off = 1; off < 1024; off <<= 1) {
        int t = (tid >= off) ? sh[tid - off] : 0;
        __syncthreads();
        sh[tid] += t;
        __syncthreads();
    }
    if (tid == 0) goff[0] = 0;
    if (tid < GG) goff[tid + 1] = sh[tid];
}

__global__ void k_fill_csr(const int* __restrict__ src, const int* __restrict__ dst,
                           const int* __restrict__ rowptr, int* cnt2, int* csr) {
    int e = blockIdx.x * blockDim.x + threadIdx.x;
    if (e < EE) {
        int d = dst[e];
        int pos = rowptr[d] + atomicAdd(&cnt2[d], 1);
        csr[pos] = src[e];
    }
}

// ---------------- weights prep: W images + projection tables -----------------
__global__ void k_weights(const float* __restrict__ gcn_W, unsigned char* __restrict__ img,
                          const float* __restrict__ atom_emb, const float* __restrict__ tag_emb,
                          const float* __restrict__ Wp, const float* __restrict__ bp,
                          float* P, float* Q) {
    int bid = blockIdx.x;
    int tid = threadIdx.x;
    if (bid < 1024) {
        int idx = bid * 256 + tid;            // 262144 = L*256*256
        int l = idx >> 16;
        int k = (idx >> 8) & 255;
        int n = idx & 255;
        float w = gcn_W[idx];                 // gcn_W[l][k][n]
        __nv_bfloat16 hi = __float2bfloat16(w);
        __nv_bfloat16 lo = __float2bfloat16(w - __bfloat162float(hi));
        int kc = k >> 6, kk = k & 63;
        uint32_t off = swz128((uint32_t)(n * 128 + kk * 2));
        size_t base = ((size_t)(l * 4 + kc) * 2) * 32768;
        *(__nv_bfloat16*)(img + base + off) = hi;
        *(__nv_bfloat16*)(img + base + 32768 + off) = lo;
    } else {
        int r = bid - 1024;
        int c = tid;
        if (r < 100) {
            float acc = 0.f;
            #pragma unroll 8
            for (int k = 0; k < HH; k++) acc += atom_emb[r * HH + k] * Wp[k * HH + c];
            P[r * HH + c] = acc;
        } else {
            int t = r - 100;
            if (t < 3) {
                float acc = bp[c];
                #pragma unroll
                for (int k = 0; k < TT; k++) acc += tag_emb[t * TT + k] * Wp[(HH + k) * HH + c];
                Q[t * HH + c] = acc;
            }
        }
    }
}

// ---------------- HMMA split-bf16 GEMM: C[M,256] = A[M,256] @ W --------------
// grid (2, ceil(M/128)), 256 threads, 64KB dynamic smem
#define SM_AH 0
#define SM_AL 16384
#define SM_BH 32768
#define SM_BL 49152
#define SM_GEMM 65536

__global__ __launch_bounds__(256) void k_gemm_mma(
    const float* __restrict__ A, const unsigned char* __restrict__ WimgL,
    float* __restrict__ C, int M,
    const float* __restrict__ P, const float* __restrict__ Q,
    const int* __restrict__ x, const int* __restrict__ tags,
    int fuse_embed, float* __restrict__ Aout) {
    extern __shared__ char smem[];
    const int tid = threadIdx.x;
    const int wid = tid >> 5;
    const int lane = tid & 31;
    const int wm = wid & 3;       // 0..3 : 32-row strip
    const int wn = wid >> 2;      // 0..1 : 64-col strip
    const uint32_t sb = smem_u32(smem);
    const int bm = blockIdx.y * 128;
    const int bn = blockIdx.x * 128;

    float acc[2][8][4];
    #pragma unroll
    for (int mi = 0; mi < 2; mi++)
        #pragma unroll
        for (int j = 0; j < 8; j++)
            #pragma unroll
            for (int q = 0; q < 4; q++) acc[mi][j][q] = 0.f;

    for (int kc = 0; kc < 4; kc++) {
        // ---- A tile: 128 rows x 64 cols fp32 -> bf16 hi/lo, SW128
        #pragma unroll
        for (int i = 0; i < 8; i++) {
            int slot = tid + i * 256;      // 0..2047
            int r = slot >> 4;
            int c4 = (slot & 15) << 2;     // 0..60
            int gr = bm + r;
            int col = kc * 64 + c4;
            float4 v = make_float4(0.f, 0.f, 0.f, 0.f);
            if (gr < M) {
                if (fuse_embed) {
                    int xi = x[gr], tg = tags[gr];
                    float4 p = *(const float4*)(P + (size_t)xi * HH + col);
                    float4 q = *(const float4*)(Q + (size_t)tg * HH + col);
                    v = make_float4(p.x + q.x, p.y + q.y, p.z + q.z, p.w + q.w);
                    *(float4*)(Aout + (size_t)gr * HH + col) = v;
                } else {
                    v = *(const float4*)(A + (size_t)gr * HH + col);
                }
            }
            __nv_bfloat16 h0 = __float2bfloat16(v.x);
            __nv_bfloat16 h1 = __float2bfloat16(v.y);
            __nv_bfloat16 h2 = __float2bfloat16(v.z);
            __nv_bfloat16 h3 = __float2bfloat16(v.w);
            uint32_t off = swz128((uint32_t)(r * 128 + c4 * 2));
            uint2 hv = make_uint2(
                ((uint32_t)__bfloat16_as_ushort(h1) << 16) | __bfloat16_as_ushort(h0),
                ((uint32_t)__bfloat16_as_ushort(h3) << 16) | __bfloat16_as_ushort(h2));
            uint2 lv = make_uint2(
                pack_bf16x2(v.x - __bfloat162float(h0), v.y - __bfloat162float(h1)),
                pack_bf16x2(v.z - __bfloat162float(h2), v.w - __bfloat162float(h3)));
            *(uint2*)(smem + SM_AH + off) = hv;
            *(uint2*)(smem + SM_AL + off) = lv;
        }
        // ---- B tiles: copy pre-swizzled images (16KB hi + 16KB lo slices)
        {
            const uint4* srcH = (const uint4*)(WimgL + (size_t)kc * 65536 + (size_t)bn * 128);
            const uint4* srcL = (const uint4*)(WimgL + (size_t)kc * 65536 + 32768 + (size_t)bn * 128);
            uint4* dstH = (uint4*)(smem + SM_BH);
            uint4* dstL = (uint4*)(smem + SM_BL);
            #pragma unroll
            for (int i = 0; i < 4; i++) {
                dstH[tid + i * 256] = srcH[tid + i * 256];
                dstL[tid + i * 256] = srcL[tid + i * 256];
            }
        }
        __syncthreads();

        // ---- compute: 4 k16 steps
        #pragma unroll
        for (int ks = 0; ks < 4; ks++) {
            uint32_t ah[2][4], al[2][4];
            {
                int rowa = 32 * wm + (lane & 15);
                int kb = ks * 32 + ((lane >> 4) << 4);
                uint32_t off0 = swz128((uint32_t)(rowa * 128 + kb));
                uint32_t off1 = swz128((uint32_t)((rowa + 16) * 128 + kb));
                ldsm4(ah[0], sb + SM_AH + off0);
                ldsm4(ah[1], sb + SM_AH + off1);
                ldsm4(al[0], sb + SM_AL + off0);
                ldsm4(al[1], sb + SM_AL + off1);
            }
            #pragma unroll
            for (int jp = 0; jp < 4; jp++) {
                int n0 = 64 * wn + 16 * jp;
                int nrow = n0 + ((lane >> 4) << 3) + (lane & 7);
                int kb2 = ks * 32 + (((lane >> 3) & 1) << 4);
                uint32_t offb = swz128((uint32_t)(nrow * 128 + kb2));
                uint32_t bh[4], bl[4];
                ldsm4(bh, sb + SM_BH + offb);
                ldsm4(bl, sb + SM_BL + offb);
                #pragma unroll
                for (int mi = 0; mi < 2; mi++) {
                    #pragma unroll
                    for (int jq = 0; jq < 2; jq++) {
                        float* d = acc[mi][jp * 2 + jq];
                        mma16816(d, ah[mi], bh + 2 * jq);   // hi*hi
                        mma16816(d, al[mi], bh + 2 * jq);   // lo*hi
                        mma16816(d, ah[mi], bl + 2 * jq);   // hi*lo
                    }
                }
            }
        }
        __syncthreads();
    }

    // ---- epilogue
    #pragma unroll
    for (int mi = 0; mi < 2; mi++) {
        #pragma unroll
        for (int j = 0; j < 8; j++) {
            int r0 = bm + 32 * wm + 16 * mi + (lane >> 2);
            int c = bn + 64 * wn + 8 * j + (lane & 3) * 2;
            if (r0 < M)
                *(float2*)(C + (size_t)r0 * HH + c) = make_float2(acc[mi][j][0], acc[mi][j][1]);
            int r1 = r0 + 8;
            if (r1 < M)
                *(float2*)(C + (size_t)r1 * HH + c) = make_float2(acc[mi][j][2], acc[mi][j][3]);
        }
    }
}

// ---------------- GCN aggregation (CSR, block per node) ---------------------
__global__ void k_aggregate(const float* __restrict__ hw, const float* __restrict__ dinv,
                            const int* __restrict__ rowptr, const int* __restrict__ csr,
                            const float* __restrict__ bias, float* __restrict__ agg) {
    const int v = blockIdx.x;
    const int c = threadIdx.x;
    const float dv = dinv[v];
    float acc = hw[(size_t)v * HH + c] * dv * dv;
    const int s0 = rowptr[v], s1 = rowptr[v + 1];
    __shared__ int   ssrc[256];
    __shared__ float sw[256];
    for (int base = s0; base < s1; base += 256) {
        int n = min(256, s1 - base);
        if (c < n) {
            int s = csr[base + c];
            ssrc[c] = s;
            sw[c] = dinv[s] * dv;
        }
        __syncthreads();
        #pragma unroll 4
        for (int j = 0; j < n; j++)
            acc += hw[(size_t)ssrc[j] * HH + c] * sw[j];
        __syncthreads();
    }
    agg[(size_t)v * HH + c] = acc + bias[c];
}

// ---------------- batch norm ------------------------------------------------
__global__ void k_zero_sums(float* sums) { sums[threadIdx.x] = 0.f; }

__global__ void k_bn_stats(const float* __restrict__ agg, float* sums) {
    const int c = threadIdx.x;
    float s = 0.f, s2 = 0.f;
    for (int r = blockIdx.x; r < NN; r += gridDim.x) {
        float v = agg[(size_t)r * HH + c];
        s += v;
        s2 += v * v;
    }
    atomicAdd(&sums[c], s);
    atomicAdd(&sums[HH + c], s2);
}

__global__ void k_bn_apply(const float* __restrict__ agg, const float* __restrict__ hres,
                           const float* __restrict__ sums,
                           const float* __restrict__ g, const float* __restrict__ b,
                           float* __restrict__ hout) {
    const int idx = blockIdx.x * blockDim.x + threadIdx.x;
    const int c = idx & (HH - 1);
    const float inv_n = 1.0f / (float)NN;
    float mu = sums[c] * inv_n;
    float var = sums[HH + c] * inv_n - mu * mu;
    float val = (agg[idx] - mu) * rsqrtf(var + 1e-5f) * g[c] + b[c];
    val = fmaxf(val, 0.f) + hres[idx];
    hout[idx] = val;
}

// ---------------- pooling + MLP ---------------------------------------------
__global__ void k_pool(const float* __restrict__ h, const int* __restrict__ goff,
                       float* __restrict__ pooled) {
    const int gidx = blockIdx.x;
    const int c = threadIdx.x;
    const int s = goff[gidx], e = goff[gidx + 1];
    float acc = 0.f;
    for (int r = s; r < e; r++) acc += h[(size_t)r * HH + c];
    float cnt = (float)(e - s);
    pooled[gidx * HH + c] = acc / fmaxf(cnt, 1.0f);
}

__global__ void k_mlp(const float* __restrict__ pooled,
                      const float* __restrict__ W1, const float* __restrict__ b1,
                      const float* __restrict__ W2, const float* __restrict__ b2,
                      float* __restrict__ out) {
    const int gidx = blockIdx.x;
    const int t = threadIdx.x;  // 128
    __shared__ float sp[HH];
    __shared__ float red[128];
    sp[t] = pooled[gidx * HH + t];
    sp[t + 128] = pooled[gidx * HH + t + 128];
    __syncthreads();
    float acc = b1[t];
    #pragma unroll 8
    for (int k = 0; k < HH; k++) acc += sp[k] * W1[k * 128 + t];
    acc = fmaxf(acc, 0.f);
    red[t] = acc * W2[t];
    __syncthreads();
    for (int off = 64; off > 0; off >>= 1) {
        if (t < off) red[t] += red[t + off];
        __syncthreads();
    }
    if (t == 0) out[gidx] = red[0] + b2[0];
}

// ---------------- launch ----------------------------------------------------
extern "C" void kernel_launch(void* const* d_in, const int* in_sizes, int n_in,
                              void* d_out, int out_size) {
    const int*   x        = (const int*)d_in[0];
    const int*   tags     = (const int*)d_in[1];
    const int*   eidx     = (const int*)d_in[2];
    const int*   batch    = (const int*)d_in[3];
    const float* atom_emb = (const float*)d_in[4];
    const float* tag_emb  = (const float*)d_in[5];
    const float* Wp       = (const float*)d_in[6];
    const float* bp       = (const float*)d_in[7];
    const float* gcn_W    = (const float*)d_in[8];
    const float* gcn_b    = (const float*)d_in[9];
    const float* bn_g     = (const float*)d_in[10];
    const float* bn_b     = (const float*)d_in[11];
    const float* W1       = (const float*)d_in[12];
    const float* b1       = (const float*)d_in[13];
    const float* W2       = (const float*)d_in[14];
    const float* b2       = (const float*)d_in[15];
    float* out = (float*)d_out;

    const int* src = eidx;
    const int* dst = eidx + EE;

    float *bufA, *bufB, *bufC, *dinv, *P, *Q, *sums, *pooled;
    int *cnt, *cnt2, *rowptr, *csr, *gcnt, *goff;
    unsigned char* Wimg;
    cudaGetSymbolAddress((void**)&bufA, g_bufA);
    cudaGetSymbolAddress((void**)&bufB, g_bufB);
    cudaGetSymbolAddress((void**)&bufC, g_bufC);
    cudaGetSymbolAddress((void**)&cnt, g_cnt);
    cudaGetSymbolAddress((void**)&cnt2, g_cnt2);
    cudaGetSymbolAddress((void**)&rowptr, g_rowptr);
    cudaGetSymbolAddress((void**)&csr, g_csr);
    cudaGetSymbolAddress((void**)&gcnt, g_gcnt);
    cudaGetSymbolAddress((void**)&goff, g_goff);
    cudaGetSymbolAddress((void**)&dinv, g_dinv);
    cudaGetSymbolAddress((void**)&P, g_P);
    cudaGetSymbolAddress((void**)&Q, g_Q);
    cudaGetSymbolAddress((void**)&sums, g_sums);
    cudaGetSymbolAddress((void**)&pooled, g_pooled);
    cudaGetSymbolAddress((void**)&Wimg, g_Wimg);

    cudaFuncSetAttribute(k_gemm_mma, cudaFuncAttributeMaxDynamicSharedMemorySize, SM_GEMM);

    const int TB = 256;
    k_zero_init<<<(NN + TB - 1) / TB, TB>>>(cnt, cnt2, gcnt);
    k_count<<<(EE + TB - 1) / TB, TB>>>(dst, batch, cnt, gcnt);
    k_scan<<<1, 1024>>>(cnt, rowptr, dinv, gcnt, goff);
    k_fill_csr<<<(EE + TB - 1) / TB, TB>>>(src, dst, rowptr, cnt2, csr);
    k_weights<<<1024 + 103, TB>>>(gcn_W, Wimg, atom_emb, tag_emb, Wp, bp, P, Q);

    float* h  = bufA;
    float* hw = bufB;
    float* agg = bufC;
    dim3 ggrid(2, (NN + 127) / 128);
    for (int l = 0; l < LL; l++) {
        k_gemm_mma<<<ggrid, 256, SM_GEMM>>>(
            h, Wimg + (size_t)l * 8 * 32768, hw, NN,
            P, Q, x, tags, (l == 0) ? 1 : 0, bufA);
        k_zero_sums<<<1, 2 * HH>>>(sums);
        k_aggregate<<<NN, HH>>>(hw, dinv, rowptr, csr, gcn_b + l * HH, agg);
        k_bn_stats<<<512, HH>>>(agg, sums);
        k_bn_apply<<<(NN * HH) / TB, TB>>>(agg, h, sums, bn_g + l * HH, bn_b + l * HH, hw);
        float* tmp = h; h = hw; hw = tmp;
    }

    k_pool<<<GG, HH>>>(h, goff, pooled);
    k_mlp<<<GG, 128>>>(pooled, W1, b1, W2, b2, out);
    (void)in_sizes; (void)n_in; (void)out_size;
}

// round 4
// speedup vs baseline: 1.2828x; 1.0684x over previous
#include <cuda_runtime.h>
#include <cuda_bf16.h>
#include <math.h>
#include <stdint.h>

#define NN 50000
#define EE 800000
#define GG 512
#define HH 256
#define TT 32
#define LL 4

// ---------------- scratch (device globals) -----------------------------------
__device__ float g_bufA[NN * HH];
__device__ float g_bufB[NN * HH];
__device__ float g_bufC[NN * HH];
__device__ float g_bufD[NN * HH];
__device__ int   g_cnt[NN];
__device__ int   g_cnt2[NN];
__device__ int   g_rowptr[NN + 1];
__device__ int   g_csr[EE];
__device__ float g_csrw[EE];
__device__ int   g_gcnt[GG];
__device__ int   g_goff[GG + 1];
__device__ float g_dinv[NN];
__device__ float g_P[100 * HH];
__device__ float g_Q[3 * HH];
__device__ float g_sums[LL * 2 * HH];     // per-layer [sum(256), sumsq(256)]
__device__ float g_pooled[GG * HH];
// Pre-swizzled bf16 hi/lo images of W^T: [L][kc=4][split=2][32768B] = 1MB
__device__ unsigned char g_Wimg[LL * 4 * 2 * 32768];

// ---------------- helpers ----------------------------------------------------
__device__ __forceinline__ uint32_t smem_u32(const void* p) {
    uint32_t a;
    asm("{ .reg .u64 t; cvta.to.shared.u64 t, %1; cvt.u32.u64 %0, t; }" : "=r"(a) : "l"(p));
    return a;
}
__device__ __forceinline__ uint32_t swz128(uint32_t o) { return o ^ ((o >> 3) & 0x70); }

__device__ __forceinline__ void ldsm4(uint32_t* r, uint32_t addr) {
    asm volatile("ldmatrix.sync.aligned.m8n8.x4.shared.b16 {%0,%1,%2,%3}, [%4];"
        : "=r"(r[0]), "=r"(r[1]), "=r"(r[2]), "=r"(r[3]) : "r"(addr));
}
__device__ __forceinline__ void mma16816(float* d, const uint32_t* a, const uint32_t* b) {
    asm volatile("mma.sync.aligned.m16n8k16.row.col.f32.bf16.bf16.f32 "
        "{%0,%1,%2,%3}, {%4,%5,%6,%7}, {%8,%9}, {%0,%1,%2,%3};"
        : "+f"(d[0]), "+f"(d[1]), "+f"(d[2]), "+f"(d[3])
        : "r"(a[0]), "r"(a[1]), "r"(a[2]), "r"(a[3]), "r"(b[0]), "r"(b[1]));
}
__device__ __forceinline__ uint32_t pack_bf16x2(float lo, float hi) {
    __nv_bfloat16 a = __float2bfloat16(lo);
    __nv_bfloat16 b = __float2bfloat16(hi);
    return ((uint32_t)__bfloat16_as_ushort(b) << 16) | __bfloat16_as_ushort(a);
}

// ---------------- setup ------------------------------------------------------
__global__ void k_zero_init(int* cnt, int* cnt2, int* gcnt, float* sums) {
    int i = blockIdx.x * blockDim.x + threadIdx.x;
    if (i < NN) { cnt[i] = 0; cnt2[i] = 0; }
    if (i < GG) gcnt[i] = 0;
    if (i < LL * 2 * HH) sums[i] = 0.f;
}

__global__ void k_count(const int* __restrict__ dst, const int* __restrict__ batch,
                        int* cnt, int* gcnt) {
    int e = blockIdx.x * blockDim.x + threadIdx.x;
    if (e < EE) atomicAdd(&cnt[dst[e]], 1);
    if (e < NN) atomicAdd(&gcnt[batch[e]], 1);
}

// single block, shuffle-based scans: rowptr + dinv + goff
__global__ __launch_bounds__(1024) void k_scan(const int* __restrict__ cnt, int* rowptr,
                                               float* dinv, const int* __restrict__ gcnt,
                                               int* goff) {
    __shared__ int wsum[32];
    const int tid = threadIdx.x;
    const int lane = tid & 31;
    const int w = tid >> 5;
    const int CH = (NN + 1023) / 1024;          // 49
    const int beg = tid * CH;
    const int end = min(beg + CH, NN);

    int tot = 0;
    for (int i = beg; i < end; i++) tot += cnt[i];
    // block exclusive scan of tot
    int x = tot;
    #pragma unroll
    for (int o = 1; o < 32; o <<= 1) {
        int t = __shfl_up_sync(0xFFFFFFFFu, x, o);
        if (lane >= o) x += t;
    }
    if (lane == 31) wsum[w] = x;
    __syncthreads();
    if (w == 0) {
        int y = wsum[lane];
        #pragma unroll
        for (int o = 1; o < 32; o <<= 1) {
            int t = __shfl_up_sync(0xFFFFFFFFu, y, o);
            if (lane >= o) y += t;
        }
        wsum[lane] = y;
    }
    __syncthreads();
    int run = ((w > 0) ? wsum[w - 1] : 0) + x - tot;   // exclusive offset
    if (tid == 0) rowptr[0] = 0;
    for (int i = beg; i < end; i++) {
        int cv = cnt[i];
        dinv[i] = rsqrtf((float)cv + 1.0f);
        run += cv;
        rowptr[i + 1] = run;
    }
    __syncthreads();
    // goff scan: 512 entries, threads 0..511 hold one each
    int vv = (tid < GG) ? gcnt[tid] : 0;
    int xg = vv;
    #pragma unroll
    for (int o = 1; o < 32; o <<= 1) {
        int t = __shfl_up_sync(0xFFFFFFFFu, xg, o);
        if (lane >= o) xg += t;
    }
    if (lane == 31) wsum[w] = xg;
    __syncthreads();
    if (w == 0) {
        int y = wsum[lane];
        #pragma unroll
        for (int o = 1; o < 32; o <<= 1) {
            int t = __shfl_up_sync(0xFFFFFFFFu, y, o);
            if (lane >= o) y += t;
        }
        wsum[lane] = y;
    }
    __syncthreads();
    int incl = ((w > 0) ? wsum[w - 1] : 0) + xg;
    if (tid == 0) goff[0] = 0;
    if (tid < GG) goff[tid + 1] = incl;
}

__global__ void k_fill_csr(const int* __restrict__ src, const int* __restrict__ dst,
                           const int* __restrict__ rowptr, const float* __restrict__ dinv,
                           int* cnt2, int* csr, float* csrw) {
    int e = blockIdx.x * blockDim.x + threadIdx.x;
    if (e < EE) {
        int s = src[e], d = dst[e];
        int pos = rowptr[d] + atomicAdd(&cnt2[d], 1);
        csr[pos] = s;
        csrw[pos] = dinv[s] * dinv[d];
    }
}

// ---------------- weights prep: W images + projection tables -----------------
__global__ void k_weights(const float* __restrict__ gcn_W, unsigned char* __restrict__ img,
                          const float* __restrict__ atom_emb, const float* __restrict__ tag_emb,
                          const float* __restrict__ Wp, const float* __restrict__ bp,
                          float* P, float* Q) {
    int bid = blockIdx.x;
    int tid = threadIdx.x;
    if (bid < 1024) {
        int idx = bid * 256 + tid;
        int l = idx >> 16;
        int k = (idx >> 8) & 255;
        int n = idx & 255;
        float w = gcn_W[idx];
        __nv_bfloat16 hi = __float2bfloat16(w);
        __nv_bfloat16 lo = __float2bfloat16(w - __bfloat162float(hi));
        int kc = k >> 6, kk = k & 63;
        uint32_t off = swz128((uint32_t)(n * 128 + kk * 2));
        size_t base = ((size_t)(l * 4 + kc) * 2) * 32768;
        *(__nv_bfloat16*)(img + base + off) = hi;
        *(__nv_bfloat16*)(img + base + 32768 + off) = lo;
    } else {
        int r = bid - 1024;
        int c = tid;
        if (r < 100) {
            float acc = 0.f;
            #pragma unroll 8
            for (int k = 0; k < HH; k++) acc += atom_emb[r * HH + k] * Wp[k * HH + c];
            P[r * HH + c] = acc;
        } else {
            int t = r - 100;
            if (t < 3) {
                float acc = bp[c];
                #pragma unroll
                for (int k = 0; k < TT; k++) acc += tag_emb[t * TT + k] * Wp[(HH + k) * HH + c];
                Q[t * HH + c] = acc;
            }
        }
    }
}

// ---------------- HMMA split-bf16 GEMM with fused prologue -------------------
// mode 1: A = P[x]+Q[tags] (embed);  mode 2: A = relu(bn(aggA)) + hres
// Aout always written (identical duplicate writes across blockIdx.x are benign).
#define SM_AH 0
#define SM_AL 16384
#define SM_BH 32768
#define SM_BL 49152
#define SM_GEMM 65536

__global__ __launch_bounds__(256) void k_gemm_mma(
    const float* __restrict__ aggA, const float* __restrict__ hres,
    const float* __restrict__ sums, const float* __restrict__ bn_g,
    const float* __restrict__ bn_b,
    const unsigned char* __restrict__ WimgL,
    float* __restrict__ C, int M,
    const float* __restrict__ P, const float* __restrict__ Q,
    const int* __restrict__ x, const int* __restrict__ tags,
    int mode, float* __restrict__ Aout) {
    extern __shared__ char smem[];
    const int tid = threadIdx.x;
    const int wid = tid >> 5;
    const int lane = tid & 31;
    const int wm = wid & 3;
    const int wn = wid >> 2;
    const uint32_t sb = smem_u32(smem);
    const int bm = blockIdx.y * 128;
    const int bn = blockIdx.x * 128;
    const int c4 = (tid & 15) << 2;       // constant channel group per thread

    float acc[2][8][4];
    #pragma unroll
    for (int mi = 0; mi < 2; mi++)
        #pragma unroll
        for (int j = 0; j < 8; j++)
            #pragma unroll
            for (int q = 0; q < 4; q++) acc[mi][j][q] = 0.f;

    const float inv_n = 1.0f / (float)NN;

    for (int kc = 0; kc < 4; kc++) {
        const int col = kc * 64 + c4;
        // hoisted BN params for this thread's channels
        float mu0 = 0.f, mu1 = 0.f, mu2 = 0.f, mu3 = 0.f;
        float rg0 = 0.f, rg1 = 0.f, rg2 = 0.f, rg3 = 0.f;
        float bb0 = 0.f, bb1 = 0.f, bb2 = 0.f, bb3 = 0.f;
        if (mode == 2) {
            mu0 = sums[col + 0] * inv_n;
            mu1 = sums[col + 1] * inv_n;
            mu2 = sums[col + 2] * inv_n;
            mu3 = sums[col + 3] * inv_n;
            float v0 = sums[HH + col + 0] * inv_n - mu0 * mu0;
            float v1 = sums[HH + col + 1] * inv_n - mu1 * mu1;
            float v2 = sums[HH + col + 2] * inv_n - mu2 * mu2;
            float v3 = sums[HH + col + 3] * inv_n - mu3 * mu3;
            rg0 = rsqrtf(v0 + 1e-5f) * bn_g[col + 0];
            rg1 = rsqrtf(v1 + 1e-5f) * bn_g[col + 1];
            rg2 = rsqrtf(v2 + 1e-5f) * bn_g[col + 2];
            rg3 = rsqrtf(v3 + 1e-5f) * bn_g[col + 3];
            bb0 = bn_b[col + 0];
            bb1 = bn_b[col + 1];
            bb2 = bn_b[col + 2];
            bb3 = bn_b[col + 3];
        }
        // ---- A tile: compute + convert to bf16 hi/lo, SW128
        #pragma unroll
        for (int i = 0; i < 8; i++) {
            int r = (tid >> 4) + i * 16;
            int gr = bm + r;
            float4 v = make_float4(0.f, 0.f, 0.f, 0.f);
            if (gr < M) {
                if (mode == 1) {
                    int xi = x[gr], tg = tags[gr];
                    float4 p = *(const float4*)(P + (size_t)xi * HH + col);
                    float4 q = *(const float4*)(Q + (size_t)tg * HH + col);
                    v = make_float4(p.x + q.x, p.y + q.y, p.z + q.z, p.w + q.w);
                } else {
                    float4 a = *(const float4*)(aggA + (size_t)gr * HH + col);
                    float4 rr = *(const float4*)(hres + (size_t)gr * HH + col);
                    v.x = fmaxf((a.x - mu0) * rg0 + bb0, 0.f) + rr.x;
                    v.y = fmaxf((a.y - mu1) * rg1 + bb1, 0.f) + rr.y;
                    v.z = fmaxf((a.z - mu2) * rg2 + bb2, 0.f) + rr.z;
                    v.w = fmaxf((a.w - mu3) * rg3 + bb3, 0.f) + rr.w;
                }
                *(float4*)(Aout + (size_t)gr * HH + col) = v;
            }
            __nv_bfloat16 h0 = __float2bfloat16(v.x);
            __nv_bfloat16 h1 = __float2bfloat16(v.y);
            __nv_bfloat16 h2 = __float2bfloat16(v.z);
            __nv_bfloat16 h3 = __float2bfloat16(v.w);
            uint32_t off = swz128((uint32_t)(r * 128 + c4 * 2));
            uint2 hv = make_uint2(
                ((uint32_t)__bfloat16_as_ushort(h1) << 16) | __bfloat16_as_ushort(h0),
                ((uint32_t)__bfloat16_as_ushort(h3) << 16) | __bfloat16_as_ushort(h2));
            uint2 lv = make_uint2(
                pack_bf16x2(v.x - __bfloat162float(h0), v.y - __bfloat162float(h1)),
                pack_bf16x2(v.z - __bfloat162float(h2), v.w - __bfloat162float(h3)));
            *(uint2*)(smem + SM_AH + off) = hv;
            *(uint2*)(smem + SM_AL + off) = lv;
        }
        // ---- B tiles (pre-swizzled)
        {
            const uint4* srcH = (const uint4*)(WimgL + (size_t)kc * 65536 + (size_t)bn * 128);
            const uint4* srcL = (const uint4*)(WimgL + (size_t)kc * 65536 + 32768 + (size_t)bn * 128);
            uint4* dstH = (uint4*)(smem + SM_BH);
            uint4* dstL = (uint4*)(smem + SM_BL);
            #pragma unroll
            for (int i = 0; i < 4; i++) {
                dstH[tid + i * 256] = srcH[tid + i * 256];
                dstL[tid + i * 256] = srcL[tid + i * 256];
            }
        }
        __syncthreads();

        #pragma unroll
        for (int ks = 0; ks < 4; ks++) {
            uint32_t ah[2][4], al[2][4];
            {
                int rowa = 32 * wm + (lane & 15);
                int kb = ks * 32 + ((lane >> 4) << 4);
                uint32_t off0 = swz128((uint32_t)(rowa * 128 + kb));
                uint32_t off1 = swz128((uint32_t)((rowa + 16) * 128 + kb));
                ldsm4(ah[0], sb + SM_AH + off0);
                ldsm4(ah[1], sb + SM_AH + off1);
                ldsm4(al[0], sb + SM_AL + off0);
                ldsm4(al[1], sb + SM_AL + off1);
            }
            #pragma unroll
            for (int jp = 0; jp < 4; jp++) {
                int n0 = 64 * wn + 16 * jp;
                int nrow = n0 + ((lane >> 4) << 3) + (lane & 7);
                int kb2 = ks * 32 + (((lane >> 3) & 1) << 4);
                uint32_t offb = swz128((uint32_t)(nrow * 128 + kb2));
                uint32_t bh[4], bl[4];
                ldsm4(bh, sb + SM_BH + offb);
                ldsm4(bl, sb + SM_BL + offb);
                #pragma unroll
                for (int mi = 0; mi < 2; mi++) {
                    #pragma unroll
                    for (int jq = 0; jq < 2; jq++) {
                        float* d = acc[mi][jp * 2 + jq];
                        mma16816(d, ah[mi], bh + 2 * jq);
                        mma16816(d, al[mi], bh + 2 * jq);
                        mma16816(d, ah[mi], bl + 2 * jq);
                    }
                }
            }
        }
        __syncthreads();
    }

    #pragma unroll
    for (int mi = 0; mi < 2; mi++) {
        #pragma unroll
        for (int j = 0; j < 8; j++) {
            int r0 = bm + 32 * wm + 16 * mi + (lane >> 2);
            int c = bn + 64 * wn + 8 * j + (lane & 3) * 2;
            if (r0 < M)
                *(float2*)(C + (size_t)r0 * HH + c) = make_float2(acc[mi][j][0], acc[mi][j][1]);
            int r1 = r0 + 8;
            if (r1 < M)
                *(float2*)(C + (size_t)r1 * HH + c) = make_float2(acc[mi][j][2], acc[mi][j][3]);
        }
    }
}

// ---------------- aggregation + fused BN stats -------------------------------
__global__ __launch_bounds__(256) void k_aggregate(
    const float* __restrict__ hw, const float* __restrict__ dinv,
    const int* __restrict__ rowptr, const int* __restrict__ csr,
    const float* __restrict__ csrw, const float* __restrict__ bias,
    float* __restrict__ agg, float* __restrict__ sums) {
    const int c = threadIdx.x;
    const float bia = bias[c];
    float s = 0.f, s2 = 0.f;
    __shared__ int   ssrc[256];
    __shared__ float sw[256];
    for (int v = blockIdx.x; v < NN; v += gridDim.x) {
        const float dv = dinv[v];
        float acc = hw[(size_t)v * HH + c] * dv * dv;
        const int s0 = rowptr[v], s1 = rowptr[v + 1];
        for (int base = s0; base < s1; base += 256) {
            int n = min(256, s1 - base);
            if (c < n) {
                ssrc[c] = csr[base + c];
                sw[c] = csrw[base + c];
            }
            __syncthreads();
            #pragma unroll 4
            for (int j = 0; j < n; j++)
                acc += hw[(size_t)ssrc[j] * HH + c] * sw[j];
            __syncthreads();
        }
        float val = acc + bia;
        agg[(size_t)v * HH + c] = val;
        s += val;
        s2 += val * val;
    }
    atomicAdd(&sums[c], s);
    atomicAdd(&sums[HH + c], s2);
}

// ---------------- pooling (fused final BN) + MLP -----------------------------
__global__ void k_pool(const float* __restrict__ agg, const float* __restrict__ hres,
                       const float* __restrict__ sums, const float* __restrict__ bn_g,
                       const float* __restrict__ bn_b, const int* __restrict__ goff,
                       float* __restrict__ pooled) {
    const int gidx = blockIdx.x;
    const int c = threadIdx.x;
    const float inv_n = 1.0f / (float)NN;
    const float mu = sums[c] * inv_n;
    const float var = sums[HH + c] * inv_n - mu * mu;
    const float rg = rsqrtf(var + 1e-5f) * bn_g[c];
    const float bb = bn_b[c];
    const int s = goff[gidx], e = goff[gidx + 1];
    float acc = 0.f;
    for (int r = s; r < e; r++) {
        float val = fmaxf((agg[(size_t)r * HH + c] - mu) * rg + bb, 0.f)
                  + hres[(size_t)r * HH + c];
        acc += val;
    }
    float cnt = (float)(e - s);
    pooled[gidx * HH + c] = acc / fmaxf(cnt, 1.0f);
}

__global__ void k_mlp(const float* __restrict__ pooled,
                      const float* __restrict__ W1, const float* __restrict__ b1,
                      const float* __restrict__ W2, const float* __restrict__ b2,
                      float* __restrict__ out) {
    const int gidx = blockIdx.x;
    const int t = threadIdx.x;  // 128
    __shared__ float sp[HH];
    __shared__ float red[128];
    sp[t] = pooled[gidx * HH + t];
    sp[t + 128] = pooled[gidx * HH + t + 128];
    __syncthreads();
    float acc = b1[t];
    #pragma unroll 8
    for (int k = 0; k < HH; k++) acc += sp[k] * W1[k * 128 + t];
    acc = fmaxf(acc, 0.f);
    red[t] = acc * W2[t];
    __syncthreads();
    for (int off = 64; off > 0; off >>= 1) {
        if (t < off) red[t] += red[t + off];
        __syncthreads();
    }
    if (t == 0) out[gidx] = red[0] + b2[0];
}

// ---------------- launch ----------------------------------------------------
extern "C" void kernel_launch(void* const* d_in, const int* in_sizes, int n_in,
                              void* d_out, int out_size) {
    const int*   x        = (const int*)d_in[0];
    const int*   tags     = (const int*)d_in[1];
    const int*   eidx     = (const int*)d_in[2];
    const int*   batch    = (const int*)d_in[3];
    const float* atom_emb = (const float*)d_in[4];
    const float* tag_emb  = (const float*)d_in[5];
    const float* Wp       = (const float*)d_in[6];
    const float* bp       = (const float*)d_in[7];
    const float* gcn_W    = (const float*)d_in[8];
    const float* gcn_b    = (const float*)d_in[9];
    const float* bn_g     = (const float*)d_in[10];
    const float* bn_b     = (const float*)d_in[11];
    const float* W1       = (const float*)d_in[12];
    const float* b1       = (const float*)d_in[13];
    const float* W2       = (const float*)d_in[14];
    const float* b2       = (const float*)d_in[15];
    float* out = (float*)d_out;

    const int* src = eidx;
    const int* dst = eidx + EE;

    float *bufA, *bufB, *bufC, *bufD, *dinv, *P, *Q, *sums, *pooled, *csrw;
    int *cnt, *cnt2, *rowptr, *csr, *gcnt, *goff;
    unsigned char* Wimg;
    cudaGetSymbolAddress((void**)&bufA, g_bufA);
    cudaGetSymbolAddress((void**)&bufB, g_bufB);
    cudaGetSymbolAddress((void**)&bufC, g_bufC);
    cudaGetSymbolAddress((void**)&bufD, g_bufD);
    cudaGetSymbolAddress((void**)&cnt, g_cnt);
    cudaGetSymbolAddress((void**)&cnt2, g_cnt2);
    cudaGetSymbolAddress((void**)&rowptr, g_rowptr);
    cudaGetSymbolAddress((void**)&csr, g_csr);
    cudaGetSymbolAddress((void**)&csrw, g_csrw);
    cudaGetSymbolAddress((void**)&gcnt, g_gcnt);
    cudaGetSymbolAddress((void**)&goff, g_goff);
    cudaGetSymbolAddress((void**)&dinv, g_dinv);
    cudaGetSymbolAddress((void**)&P, g_P);
    cudaGetSymbolAddress((void**)&Q, g_Q);
    cudaGetSymbolAddress((void**)&sums, g_sums);
    cudaGetSymbolAddress((void**)&pooled, g_pooled);
    cudaGetSymbolAddress((void**)&Wimg, g_Wimg);

    cudaFuncSetAttribute(k_gemm_mma, cudaFuncAttributeMaxDynamicSharedMemorySize, SM_GEMM);

    const int TB = 256;
    k_zero_init<<<(NN + TB - 1) / TB, TB>>>(cnt, cnt2, gcnt, sums);
    k_count<<<(EE + TB - 1) / TB, TB>>>(dst, batch, cnt, gcnt);
    k_scan<<<1, 1024>>>(cnt, rowptr, dinv, gcnt, goff);
    k_fill_csr<<<(EE + TB - 1) / TB, TB>>>(src, dst, rowptr, dinv, cnt2, csr, csrw);
    k_weights<<<1024 + 103, TB>>>(gcn_W, Wimg, atom_emb, tag_emb, Wp, bp, P, Q);

    dim3 ggrid(2, (NN + 127) / 128);
    const int AGG_GRID = 2048;

    // layer 0: embed-fused GEMM -> h0=bufA, hw=bufB; aggregate -> bufC, sums[0]
    k_gemm_mma<<<ggrid, 256, SM_GEMM>>>(nullptr, nullptr, nullptr, nullptr, nullptr,
        Wimg, bufB, NN, P, Q, x, tags, 1, bufA);
    k_aggregate<<<AGG_GRID, 256>>>(bufB, dinv, rowptr, csr, csrw, gcn_b, bufC, sums);

    // layers 1..3: bn-fused GEMM
    float* hres = bufA;       // h_{l-1}
    float* hnew = bufD;
    for (int l = 1; l < LL; l++) {
        k_gemm_mma<<<ggrid, 256, SM_GEMM>>>(
            bufC, hres, sums + (size_t)(l - 1) * 2 * HH,
            bn_g + (size_t)(l - 1) * HH, bn_b + (size_t)(l - 1) * HH,
            Wimg + (size_t)l * 8 * 32768, bufB, NN, P, Q, x, tags, 2, hnew);
        k_aggregate<<<AGG_GRID, 256>>>(bufB, dinv, rowptr, csr, csrw,
                                       gcn_b + (size_t)l * HH, bufC,
                                       sums + (size_t)l * 2 * HH);
        float* tmp = hres; hres = hnew; hnew = tmp;
    }

    // final: pool with fused BN(layer3)+residual(hres=h3's residual input)
    k_pool<<<GG, HH>>>(bufC, hres, sums + (size_t)(LL - 1) * 2 * HH,
                       bn_g + (size_t)(LL - 1) * HH, bn_b + (size_t)(LL - 1) * HH,
                       goff, pooled);
    k_mlp<<<GG, 128>>>(pooled, W1, b1, W2, b2, out);
    (void)in_sizes; (void)n_in; (void)out_size;
}